// round 5
// baseline (speedup 1.0000x reference)
#include <cuda_runtime.h>

#define N_POS 8192
#define N_NEG 4000
#define N_TOT (N_POS + N_POS * N_NEG)   // 32,776,192 = 8192*4001
#define NT4   (N_TOT / 4)               // 8,194,048 vec4 tiles

constexpr int TPB2 = 512;               // pass-2 block size (16 warps)
constexpr int NB2  = 296;               // pass-2 blocks (2/SM, 64KB smem each)

// Static scratch (allocations forbidden).
__device__ float        g_pos[N_POS];
__device__ unsigned int g_rank[N_POS];  // single shared count array (REDG target)

// ---------------- Pass 1: scan index (131MB), scatter pos, zero g_rank -------
constexpr int TPB1  = 256;
constexpr int EPT1  = 16;
constexpr int NBLK1 = N_TOT / (TPB1 * EPT1);   // 8002, exact

__global__ __launch_bounds__(TPB1) void k_scatter_pos(
    const int*   __restrict__ idx,
    const float* __restrict__ pv)
{
    unsigned int base = (blockIdx.x * TPB1 + threadIdx.x) * EPT1;
    const int4* p4 = reinterpret_cast<const int4*>(idx + base);
    int4 r[4];
#pragma unroll
    for (int q = 0; q < 4; q++) r[q] = p4[q];
#pragma unroll
    for (int q = 0; q < 4; q++) {
        int js[4] = {r[q].x, r[q].y, r[q].z, r[q].w};
#pragma unroll
        for (int k = 0; k < 4; k++) {
            unsigned int j = (unsigned int)js[k];
            if (j < N_POS) g_pos[j] = pv[base + q * 4 + k];  // rare: 8192/32.7M
        }
    }
    if (blockIdx.x == 0) {
        for (int i = threadIdx.x; i < N_POS; i += TPB1) g_rank[i] = 0u;
    }
}

// ---------------- Pass 2: smem pos table, hybrid smem/global counting --------
// Rarer-side counting: pos>0 -> count (v >  pos), rank = 1+cnt
//                      pos<=0-> count (v <= pos), rank = 4001-cnt
// Warps 0 mod 4 accumulate in the block's smem histogram (shared pipe);
// other warps REDG straight into g_rank (LSU/L2 pipe) -> pipe balance.
__global__ __launch_bounds__(TPB2) void k_count(
    const int*   __restrict__ idx,
    const float* __restrict__ pv)
{
    __shared__ float        spos[N_POS];   // 32KB
    __shared__ unsigned int hist[N_POS];   // 32KB

    for (int i = threadIdx.x; i < N_POS; i += TPB2) {
        spos[i] = g_pos[i];                // coalesced table load
        hist[i] = 0u;
    }
    __syncthreads();

    const bool use_smem = ((threadIdx.x >> 5) & 3) == 0;   // 4 of 16 warps

    const int4*   idx4 = reinterpret_cast<const int4*>(idx);
    const float4* pv4  = reinterpret_cast<const float4*>(pv);

    for (unsigned int t = blockIdx.x * TPB2 + threadIdx.x; t < NT4; t += NB2 * TPB2) {
        int4   a = idx4[t];
        float4 v = pv4[t];
        int   js[4] = {a.x, a.y, a.z, a.w};
        float vs[4] = {v.x, v.y, v.z, v.w};
#pragma unroll
        for (int k = 0; k < 4; k++) {
            unsigned int j = (unsigned int)js[k];
            if (j >= N_POS) {
                unsigned int p = (j - N_POS) / N_NEG;   // const-div -> umulhi
                float pos = spos[p];                     // LDS
                if ((vs[k] > pos) == (pos > 0.0f)) {     // rarer side (~25%)
                    if (use_smem) atomicAdd(&hist[p], 1u);    // ATOMS
                    else          atomicAdd(&g_rank[p], 1u);  // REDG (L2)
                }
            }
        }
    }
    __syncthreads();

    // Sparse flush of the smem histogram straight into g_rank (REDG).
    for (int i = threadIdx.x; i < N_POS; i += TPB2) {
        unsigned int c = hist[i];
        if (c) atomicAdd(&g_rank[i], c);
    }
}

// ---------------- Finalize: one block, ranks -> sample_mrr + mean ------------
__global__ __launch_bounds__(1024) void k_finalize(float* __restrict__ out)
{
    __shared__ float ssum[1024];
    float s = 0.0f;
    for (int p = threadIdx.x; p < N_POS; p += 1024) {
        float pos = g_pos[p];
        unsigned int cnt = g_rank[p];
        unsigned int rank = (pos > 0.0f) ? (1u + cnt)
                                         : (unsigned int)(N_NEG + 1) - cnt;
        float smrr = 1.0f / (float)rank;
        out[1 + p] = smrr;
        s += smrr;
    }
    ssum[threadIdx.x] = s;
    __syncthreads();
    for (int off = 512; off > 0; off >>= 1) {
        if (threadIdx.x < off) ssum[threadIdx.x] += ssum[threadIdx.x + off];
        __syncthreads();
    }
    if (threadIdx.x == 0) out[0] = ssum[0] / (float)N_POS;
}

extern "C" void kernel_launch(void* const* d_in, const int* in_sizes, int n_in,
                              void* d_out, int out_size)
{
    const float* pv  = (const float*)d_in[0];
    const int*   idx = (const int*)d_in[1];
    float* out = (float*)d_out;
    (void)in_sizes; (void)n_in; (void)out_size;

    k_scatter_pos<<<NBLK1, TPB1>>>(idx, pv);
    k_count<<<NB2, TPB2>>>(idx, pv);
    k_finalize<<<1, 1024>>>(out);
}

// round 6
// speedup vs baseline: 1.3876x; 1.3876x over previous
#include <cuda_runtime.h>

#define N_POS 8192
#define N_NEG 4000
#define N_TOT (N_POS + N_POS * N_NEG)   // 32,776,192 = 8192*4001
#define NT4   (N_TOT / 4)               // 8,194,048 vec4 tiles

constexpr int TPB2 = 512;               // pass-2 block size (16 warps)
constexpr int NB2  = 296;               // pass-2 blocks (2/SM, 64KB smem each)
constexpr int NREP = 32;                // global counter replicas
constexpr int NFB  = 32;                // finalize blocks

// Static scratch (allocations forbidden).
__device__ float        g_pos[N_POS];
__device__ unsigned int g_rep[NREP * N_POS];     // replicated REDG counters, 1MB
__device__ unsigned int g_hist[NB2 * N_POS];     // per-block smem-hist dumps, 9.7MB
__device__ float        g_psum[NFB];
__device__ unsigned int g_ticket;

// ---------------- Pass 1: scan index (131MB), scatter pos, zero counters -----
constexpr int TPB1  = 256;
constexpr int EPT1  = 16;
constexpr int NBLK1 = N_TOT / (TPB1 * EPT1);   // 8002, exact

__global__ __launch_bounds__(TPB1) void k_scatter_pos(
    const int*   __restrict__ idx,
    const float* __restrict__ pv)
{
    unsigned int base = (blockIdx.x * TPB1 + threadIdx.x) * EPT1;
    const int4* p4 = reinterpret_cast<const int4*>(idx + base);
    int4 r[4];
#pragma unroll
    for (int q = 0; q < 4; q++) r[q] = p4[q];
#pragma unroll
    for (int q = 0; q < 4; q++) {
        int js[4] = {r[q].x, r[q].y, r[q].z, r[q].w};
#pragma unroll
        for (int k = 0; k < 4; k++) {
            unsigned int j = (unsigned int)js[k];
            if (j < N_POS) g_pos[j] = pv[base + q * 4 + k];  // rare: 8192/32.7M
        }
    }
    // Blocks 0..127 zero the replica array (262144 words); block 0 resets ticket.
    if (blockIdx.x < 128) {
        unsigned int i0 = blockIdx.x * TPB1 + threadIdx.x;
        for (unsigned int i = i0; i < NREP * N_POS; i += 128 * TPB1) g_rep[i] = 0u;
        if (blockIdx.x == 0 && threadIdx.x == 0) g_ticket = 0u;
    }
}

// ---------------- Pass 2: smem pos table, hybrid ATOMS / replicated REDG -----
// Rarer-side counting: pos>0 -> count (v >  pos), rank = 1+cnt
//                      pos<=0-> count (v <= pos), rank = 4001-cnt
// Even warps -> block smem histogram (shared pipe, ATOMS).
// Odd  warps -> g_rep[blockIdx&31] (LSU/L2 pipe, REDG, ~16 hits/address).
__global__ __launch_bounds__(TPB2) void k_count(
    const int*   __restrict__ idx,
    const float* __restrict__ pv)
{
    __shared__ float        spos[N_POS];   // 32KB
    __shared__ unsigned int hist[N_POS];   // 32KB

    for (int i = threadIdx.x; i < N_POS; i += TPB2) {
        spos[i] = g_pos[i];                // coalesced table load
        hist[i] = 0u;
    }
    __syncthreads();

    const bool use_smem = ((threadIdx.x >> 5) & 1) == 0;   // 8 of 16 warps
    unsigned int* rep = g_rep + (size_t)(blockIdx.x & (NREP - 1)) * N_POS;

    const int4*   idx4 = reinterpret_cast<const int4*>(idx);
    const float4* pv4  = reinterpret_cast<const float4*>(pv);

    for (unsigned int t = blockIdx.x * TPB2 + threadIdx.x; t < NT4; t += NB2 * TPB2) {
        int4   a = idx4[t];
        float4 v = pv4[t];
        int   js[4] = {a.x, a.y, a.z, a.w};
        float vs[4] = {v.x, v.y, v.z, v.w};
#pragma unroll
        for (int k = 0; k < 4; k++) {
            unsigned int j = (unsigned int)js[k];
            if (j >= N_POS) {
                unsigned int p = (j - N_POS) / N_NEG;   // const-div -> umulhi
                float pos = spos[p];                     // LDS
                if ((vs[k] > pos) == (pos > 0.0f)) {     // rarer side (~25%)
                    if (use_smem) atomicAdd(&hist[p], 1u);   // ATOMS
                    else          atomicAdd(&rep[p],  1u);   // REDG, low-contention
                }
            }
        }
    }
    __syncthreads();

    unsigned int* row = g_hist + (size_t)blockIdx.x * N_POS;
    for (int i = threadIdx.x; i < N_POS; i += TPB2) row[i] = hist[i];  // coalesced
}

// ---------------- Finalize: reduce hist+replicas, smrr, mean (ticketed) ------
__global__ __launch_bounds__(256) void k_final(float* __restrict__ out)
{
    int p = blockIdx.x * 256 + threadIdx.x;   // 32 x 256 = 8192
    unsigned int cnt = 0;
#pragma unroll 4
    for (int b = 0; b < NB2; b++)  cnt += g_hist[(size_t)b * N_POS + p];
#pragma unroll
    for (int r = 0; r < NREP; r++) cnt += g_rep[(size_t)r * N_POS + p];

    float pos = g_pos[p];
    unsigned int rank = (pos > 0.0f) ? (1u + cnt)
                                     : (unsigned int)(N_NEG + 1) - cnt;
    float smrr = 1.0f / (float)rank;
    out[1 + p] = smrr;

    __shared__ float ssum[256];
    ssum[threadIdx.x] = smrr;
    __syncthreads();
    for (int off = 128; off > 0; off >>= 1) {
        if (threadIdx.x < off) ssum[threadIdx.x] += ssum[threadIdx.x + off];
        __syncthreads();
    }
    __shared__ bool last;
    if (threadIdx.x == 0) {
        g_psum[blockIdx.x] = ssum[0];
        __threadfence();
        last = (atomicAdd(&g_ticket, 1u) == NFB - 1);
    }
    __syncthreads();
    if (last && threadIdx.x == 0) {
        float s = 0.0f;
        for (int i = 0; i < NFB; i++) s += g_psum[i];
        out[0] = s / (float)N_POS;
    }
}

extern "C" void kernel_launch(void* const* d_in, const int* in_sizes, int n_in,
                              void* d_out, int out_size)
{
    const float* pv  = (const float*)d_in[0];
    const int*   idx = (const int*)d_in[1];
    float* out = (float*)d_out;
    (void)in_sizes; (void)n_in; (void)out_size;

    k_scatter_pos<<<NBLK1, TPB1>>>(idx, pv);
    k_count<<<NB2, TPB2>>>(idx, pv);
    k_final<<<NFB, 256>>>(out);
}

// round 10
// speedup vs baseline: 1.4348x; 1.0341x over previous
#include <cuda_runtime.h>

#define N_POS 8192
#define N_NEG 4000
#define N_TOT (N_POS + N_POS * N_NEG)   // 32,776,192 = 8192*4001
#define NT4   (N_TOT / 4)               // 8,194,048 vec4 tiles

constexpr int TPB2 = 512;               // pass-2 block size (16 warps)
constexpr int NB2  = 444;               // pass-2 blocks (3/SM, 64KB smem each)
constexpr int NFB  = 64;                // finalize blocks

// Static scratch (allocations forbidden).
__device__ float        g_pos[N_POS];
__device__ unsigned int g_hist[NB2 * N_POS];   // per-block histograms, 14.5MB
__device__ float        g_psum[NFB];
__device__ unsigned int g_ticket;

// ---------------- Pass 1: scan index (131MB), scatter the 8192 pos values ----
constexpr int TPB1  = 256;
constexpr int EPT1  = 16;
constexpr int NBLK1 = N_TOT / (TPB1 * EPT1);   // 8002, exact

__global__ __launch_bounds__(TPB1) void k_scatter_pos(
    const int*   __restrict__ idx,
    const float* __restrict__ pv)
{
    unsigned int base = (blockIdx.x * TPB1 + threadIdx.x) * EPT1;
    const int4* p4 = reinterpret_cast<const int4*>(idx + base);
    int4 r[4];
#pragma unroll
    for (int q = 0; q < 4; q++) r[q] = p4[q];
#pragma unroll
    for (int q = 0; q < 4; q++) {
        int js[4] = {r[q].x, r[q].y, r[q].z, r[q].w};
#pragma unroll
        for (int k = 0; k < 4; k++) {
            unsigned int j = (unsigned int)js[k];
            if (j < N_POS) g_pos[j] = pv[base + q * 4 + k];  // rare: 8192/32.7M
        }
    }
    if (blockIdx.x == 0 && threadIdx.x == 0) g_ticket = 0u;
}

// ---------------- Pass 2: smem pos table + smem histograms -------------------
// Rarer-side counting: pos>0 -> count (v >  pos), rank = 1+cnt
//                      pos<=0-> count (v <= pos), rank = 4001-cnt
__global__ __launch_bounds__(TPB2) void k_count(
    const int*   __restrict__ idx,
    const float* __restrict__ pv)
{
    __shared__ float        spos[N_POS];   // 32KB
    __shared__ unsigned int hist[N_POS];   // 32KB

    for (int i = threadIdx.x; i < N_POS; i += TPB2) {
        spos[i] = g_pos[i];                // coalesced table load
        hist[i] = 0u;
    }
    __syncthreads();

    const int4*   idx4 = reinterpret_cast<const int4*>(idx);
    const float4* pv4  = reinterpret_cast<const float4*>(pv);

    for (unsigned int t = blockIdx.x * TPB2 + threadIdx.x; t < NT4; t += NB2 * TPB2) {
        int4   a = idx4[t];
        float4 v = pv4[t];
        int   js[4] = {a.x, a.y, a.z, a.w};
        float vs[4] = {v.x, v.y, v.z, v.w};
#pragma unroll
        for (int k = 0; k < 4; k++) {
            unsigned int j = (unsigned int)js[k];
            if (j >= N_POS) {
                unsigned int p = (j - N_POS) / N_NEG;   // const-div -> umulhi
                float pos = spos[p];                     // LDS
                if ((vs[k] > pos) == (pos > 0.0f)) {     // rarer side (~25%)
                    atomicAdd(&hist[p], 1u);             // ATOMS, spread-addr
                }
            }
        }
    }
    __syncthreads();

    unsigned int* row = g_hist + (size_t)blockIdx.x * N_POS;
    for (int i = threadIdx.x; i < N_POS; i += TPB2) row[i] = hist[i];  // coalesced
}

// ---------------- Finalize: reduce hists, smrr, deterministic mean -----------
__global__ __launch_bounds__(128) void k_final(float* __restrict__ out)
{
    int p = blockIdx.x * 128 + threadIdx.x;   // 64 x 128 = 8192
    unsigned int cnt = 0;
#pragma unroll 4
    for (int b = 0; b < NB2; b++)
        cnt += g_hist[(size_t)b * N_POS + p]; // coalesced across threads

    float pos = g_pos[p];
    unsigned int rank = (pos > 0.0f) ? (1u + cnt)
                                     : (unsigned int)(N_NEG + 1) - cnt;
    float smrr = 1.0f / (float)rank;
    out[1 + p] = smrr;

    __shared__ float ssum[128];
    ssum[threadIdx.x] = smrr;
    __syncthreads();
    for (int off = 64; off > 0; off >>= 1) {
        if (threadIdx.x < off) ssum[threadIdx.x] += ssum[threadIdx.x + off];
        __syncthreads();
    }
    __shared__ bool last;
    if (threadIdx.x == 0) {
        g_psum[blockIdx.x] = ssum[0];
        __threadfence();
        last = (atomicAdd(&g_ticket, 1u) == NFB - 1);
    }
    __syncthreads();
    if (last && threadIdx.x == 0) {
        float s = 0.0f;
        for (int i = 0; i < NFB; i++) s += g_psum[i];
        out[0] = s / (float)N_POS;
    }
}

extern "C" void kernel_launch(void* const* d_in, const int* in_sizes, int n_in,
                              void* d_out, int out_size)
{
    const float* pv  = (const float*)d_in[0];
    const int*   idx = (const int*)d_in[1];
    float* out = (float*)d_out;
    (void)in_sizes; (void)n_in; (void)out_size;

    k_scatter_pos<<<NBLK1, TPB1>>>(idx, pv);
    k_count<<<NB2, TPB2>>>(idx, pv);
    k_final<<<NFB, 128>>>(out);
}

// round 11
// speedup vs baseline: 1.5831x; 1.1033x over previous
#include <cuda_runtime.h>

#define N_POS 8192
#define N_NEG 4000
#define N_TOT (N_POS + N_POS * N_NEG)   // 32,776,192 = 8192*4001
#define NT4   (N_TOT / 4)               // 8,194,048 vec4 tiles

constexpr int TPB2 = 512;               // pass-2 block size (16 warps)
constexpr int NB2  = 296;               // pass-2 blocks (2/SM, 64KB smem each)
constexpr int NFB  = 64;                // finalize blocks

// Static scratch (allocations forbidden).
__device__ float        g_pos[N_POS];
__device__ unsigned int g_hist[NB2 * N_POS];   // per-block histograms, 9.7MB
__device__ float        g_psum[NFB];
__device__ unsigned int g_ticket;

// ---------------- Pass 1: scan index (131MB), scatter the 8192 pos values ----
// Coalesced: the q-th int4 load of a warp has consecutive lanes -> 4 L1
// wavefronts per LDG.128 (was 16 with the thread-contiguous layout).
constexpr int TPB1  = 256;
constexpr int EPT1  = 32;                      // ints per thread (8 int4 loads)
constexpr int NBLK1 = N_TOT / (TPB1 * EPT1);   // 4001, exact

__global__ __launch_bounds__(TPB1) void k_scatter_pos(
    const int*   __restrict__ idx,
    const float* __restrict__ pv)
{
    const int4* idx4 = reinterpret_cast<const int4*>(idx);
    unsigned int base4 = blockIdx.x * (TPB1 * (EPT1 / 4));  // block's int4 base
    int4 r[8];
#pragma unroll
    for (int q = 0; q < 8; q++)
        r[q] = idx4[base4 + q * TPB1 + threadIdx.x];
#pragma unroll
    for (int q = 0; q < 8; q++) {
        unsigned int e0 = (base4 + q * TPB1 + threadIdx.x) * 4;
        int js[4] = {r[q].x, r[q].y, r[q].z, r[q].w};
#pragma unroll
        for (int k = 0; k < 4; k++) {
            unsigned int j = (unsigned int)js[k];
            if (j < N_POS) g_pos[j] = pv[e0 + k];   // rare: 8192/32.7M
        }
    }
    if (blockIdx.x == 0 && threadIdx.x == 0) g_ticket = 0u;
}

// ---------------- Pass 2: smem pos table + smem histograms -------------------
// Rarer-side counting: pos>0 -> count (v >  pos), rank = 1+cnt
//                      pos<=0-> count (v <= pos), rank = 4001-cnt
__global__ __launch_bounds__(TPB2) void k_count(
    const int*   __restrict__ idx,
    const float* __restrict__ pv)
{
    __shared__ float        spos[N_POS];   // 32KB
    __shared__ unsigned int hist[N_POS];   // 32KB

    for (int i = threadIdx.x; i < N_POS; i += TPB2) {
        spos[i] = g_pos[i];                // coalesced table load
        hist[i] = 0u;
    }
    __syncthreads();

    const int4*   idx4 = reinterpret_cast<const int4*>(idx);
    const float4* pv4  = reinterpret_cast<const float4*>(pv);

    for (unsigned int t = blockIdx.x * TPB2 + threadIdx.x; t < NT4; t += NB2 * TPB2) {
        int4   a = idx4[t];
        float4 v = pv4[t];
        int   js[4] = {a.x, a.y, a.z, a.w};
        float vs[4] = {v.x, v.y, v.z, v.w};
#pragma unroll
        for (int k = 0; k < 4; k++) {
            unsigned int j = (unsigned int)js[k];
            if (j >= N_POS) {
                unsigned int p = (j - N_POS) / N_NEG;   // const-div -> umulhi
                float pos = spos[p];                     // LDS
                if ((vs[k] > pos) == (pos > 0.0f)) {     // rarer side (~25%)
                    atomicAdd(&hist[p], 1u);             // ATOMS, spread-addr
                }
            }
        }
    }
    __syncthreads();

    unsigned int* row = g_hist + (size_t)blockIdx.x * N_POS;
    for (int i = threadIdx.x; i < N_POS; i += TPB2) row[i] = hist[i];  // coalesced
}

// ---------------- Finalize: reduce hists, smrr, deterministic mean -----------
__global__ __launch_bounds__(128) void k_final(float* __restrict__ out)
{
    int p = blockIdx.x * 128 + threadIdx.x;   // 64 x 128 = 8192
    unsigned int cnt = 0;
#pragma unroll 4
    for (int b = 0; b < NB2; b++)
        cnt += g_hist[(size_t)b * N_POS + p]; // coalesced across threads

    float pos = g_pos[p];
    unsigned int rank = (pos > 0.0f) ? (1u + cnt)
                                     : (unsigned int)(N_NEG + 1) - cnt;
    float smrr = 1.0f / (float)rank;
    out[1 + p] = smrr;

    __shared__ float ssum[128];
    ssum[threadIdx.x] = smrr;
    __syncthreads();
    for (int off = 64; off > 0; off >>= 1) {
        if (threadIdx.x < off) ssum[threadIdx.x] += ssum[threadIdx.x + off];
        __syncthreads();
    }
    __shared__ bool last;
    if (threadIdx.x == 0) {
        g_psum[blockIdx.x] = ssum[0];
        __threadfence();
        last = (atomicAdd(&g_ticket, 1u) == NFB - 1);
    }
    __syncthreads();
    if (last && threadIdx.x == 0) {
        float s = 0.0f;
        for (int i = 0; i < NFB; i++) s += g_psum[i];
        out[0] = s / (float)N_POS;
    }
}

extern "C" void kernel_launch(void* const* d_in, const int* in_sizes, int n_in,
                              void* d_out, int out_size)
{
    const float* pv  = (const float*)d_in[0];
    const int*   idx = (const int*)d_in[1];
    float* out = (float*)d_out;
    (void)in_sizes; (void)n_in; (void)out_size;

    k_scatter_pos<<<NBLK1, TPB1>>>(idx, pv);
    k_count<<<NB2, TPB2>>>(idx, pv);
    k_final<<<NFB, 128>>>(out);
}